// round 16
// baseline (speedup 1.0000x reference)
#include <cuda_runtime.h>
#include <cuda_fp16.h>
#include <cstdint>
#include <math.h>

#define Bv      8
#define Sv      512
#define Dv      512
#define WIDTHv  16
#define NPAD    544
#define MQKV    (Bv*NPAD)      // 4352
#define MS      (Bv*Sv)        // 4096
#define M2      (2*MS)         // 8192

#define WOFF_QKV 0
#define WOFF_WO  1572864
#define WOFF_HW  2097152
#define BOFF_QKV 0
#define BOFF_WO  3072
#define BOFF_HW  4096

// ---------------- scratch (half activations/weights) ---------------------------
__device__ __half g_x[MQKV*Dv];
__device__ __half g_qkv[MQKV*3072];
__device__ __half g_attn[2*MQKV*Dv];
__device__ __half g_h0a[M2*Dv];
__device__ __half g_h0b[M2*Dv];
__device__ __half g_wcvt[4194304];
__device__ float  g_bias[8192];

// ---------------- helpers -------------------------------------------------------
__device__ __forceinline__ uint32_t smem_u32(const void* p) {
    uint32_t a;
    asm("{ .reg .u64 t; cvta.to.shared.u64 t, %1; cvt.u32.u64 %0, t; }"
        : "=r"(a) : "l"(p));
    return a;
}
__device__ __forceinline__ void cpa16(uint32_t s, const void* g) {
    asm volatile("cp.async.cg.shared.global [%0], [%1], 16;" :: "r"(s), "l"(g));
}

// ---------------- prep (4 floats/thread, all weights+biases+pad) -------------------
#define PREP_W4   1048576
#define PREP_B    (PREP_W4 + 8192)
#define PREP_P4   (PREP_B + MQKV*Dv/4)

__global__ void prep_kernel(
    const float* __restrict__ inp,
    const float* __restrict__ lp,  const float* __restrict__ rp,
    const float* __restrict__ Wq0, const float* __restrict__ Wq1,
    const float* __restrict__ Wo0, const float* __restrict__ Wo1,
    const float* __restrict__ Wh0, const float* __restrict__ Wh1,
    const float* __restrict__ bq0, const float* __restrict__ bq1,
    const float* __restrict__ bo0, const float* __restrict__ bo1,
    const float* __restrict__ bh0, const float* __restrict__ bh1)
{
    int t = blockIdx.x * 256 + threadIdx.x;
    if (t < PREP_W4) {
        int i = t * 4;
        const float* src;
        if (i < WOFF_WO) {
            int n = i >> 9, k = i & 511;
            int d = n >= 1536;
            src = (d ? Wq1 : Wq0) + (n - d * 1536) * 512 + k;
        } else if (i < WOFF_HW) {
            int j = i - WOFF_WO;
            int n = j >> 9, k = j & 511;
            int d = n >= 512;
            src = (d ? Wo1 : Wo0) + (n - d * 512) * 512 + k;
        } else {
            int j = i - WOFF_HW;
            int blk = j >> 19;
            int d = blk >> 1, l = blk & 1;
            int rw = (j >> 9) & 1023, k = j & 511;
            int c = rw >> 1, wh = rw & 1;
            src = (d ? Wh1 : Wh0) + l * 524288 + (wh * 512 + c) * 512 + k;
        }
        float4 v = *(const float4*)src;
        __half2 a = __floats2half2_rn(v.x, v.y);
        __half2 b = __floats2half2_rn(v.z, v.w);
        uint2 u = {*(uint32_t*)&a, *(uint32_t*)&b};
        *(uint2*)(g_wcvt + i) = u;
    } else if (t < PREP_B) {
        int j = t - PREP_W4;
        float v;
        if (j < BOFF_WO) {
            int d = j >= 1536;
            v = (d ? bq1 : bq0)[j - d * 1536];
        } else if (j < BOFF_HW) {
            int jj = j - BOFF_WO;
            int d = jj >= 512;
            v = (d ? bo1 : bo0)[jj - d * 512];
        } else {
            int jj = j - BOFF_HW;
            int blk = jj >> 10;
            int d = blk >> 1, l = blk & 1;
            int r = jj & 1023;
            int c = r >> 1, wh = r & 1;
            v = (d ? bh1 : bh0)[l * 1024 + wh * 512 + c];
        }
        g_bias[j] = v;
    } else if (t < PREP_P4) {
        int idx = (t - PREP_B) * 4;
        int d = idx & (Dv - 1);
        int p = (idx / Dv) % NPAD;
        int b = idx / (Dv * NPAD);
        const float* src;
        if (p < WIDTHv)            src = lp + p * Dv + d;
        else if (p < WIDTHv + Sv)  src = inp + ((size_t)b * Sv + (p - WIDTHv)) * Dv + d;
        else                       src = rp + (p - WIDTHv - Sv) * Dv + d;
        float4 v = *(const float4*)src;
        __half2 a = __floats2half2_rn(v.x, v.y);
        __half2 bb = __floats2half2_rn(v.z, v.w);
        uint2 u = {*(uint32_t*)&a, *(uint32_t*)&bb};
        *(uint2*)(g_x + idx) = u;
    }
}

// ---------------- fp16 mma GEMM: BM=128 BN=64 BK=64, kk-pipelined fragments --------
#define ABYT   18432
#define STGB   27648

__global__ __launch_bounds__(128) void gemm_mma(
    const __half* __restrict__ A, const __half* __restrict__ W,
    const float* __restrict__ bias, void* __restrict__ Cout,
    int Nn, int amap, int ncol0,
    int emode, long total, int copies, int coloff)
{
    extern __shared__ char dsm[];
    uint32_t sbase = smem_u32(dsm);
    int tid = threadIdx.x;
    int m0 = blockIdx.y * 128, n0 = blockIdx.x * 64;

    long aoff[8]; int woff[4];
    uint32_t sa[8], sw[4];
#pragma unroll
    for (int i = 0; i < 8; i++) {
        int id = tid + 128 * i;
        int row = id >> 3, seg = id & 7;
        int gm = m0 + row;
        long ar = amap ? ((long)(gm >> 9) * NPAD + WIDTHv + (gm & 511)) : (long)gm;
        aoff[i] = ar * 512 + seg * 8;
        sa[i] = (uint32_t)(row * 144 + seg * 16);
    }
#pragma unroll
    for (int i = 0; i < 4; i++) {
        int id = tid + 128 * i;
        int row = id >> 3, seg = id & 7;
        woff[i] = (n0 + row) * 512 + seg * 8;
        sw[i] = (uint32_t)(row * 144 + seg * 16);
    }

#pragma unroll
    for (int s = 0; s < 2; s++) {
        uint32_t ab = sbase + (uint32_t)s * STGB;
#pragma unroll
        for (int i = 0; i < 8; i++) cpa16(ab + sa[i],        A + aoff[i] + s * 64);
#pragma unroll
        for (int i = 0; i < 4; i++) cpa16(ab + ABYT + sw[i], W + woff[i] + s * 64);
        asm volatile("cp.async.commit_group;");
    }

    int wid = tid >> 5, lane = tid & 31;
    int wm = wid >> 1, wn = wid & 1;
    int grp = lane >> 2, tig = lane & 3;

    float acc[4][4][4];
#pragma unroll
    for (int mt = 0; mt < 4; mt++)
#pragma unroll
        for (int nt = 0; nt < 4; nt++)
#pragma unroll
            for (int r = 0; r < 4; r++) acc[mt][nt][r] = 0.f;

    uint32_t a2[2][4][4], b2[2][4][2];

    for (int c = 0; c < 8; c++) {
        if (c >= 7) asm volatile("cp.async.wait_group 0;" ::: "memory");
        else        asm volatile("cp.async.wait_group 1;" ::: "memory");
        __syncthreads();

        const uint32_t* asu = (const uint32_t*)(dsm + (size_t)(c & 1) * STGB);
        const uint32_t* wsu = asu + ABYT / 4;

        // preload kk=0 fragments
        {
            int kb = tig;
#pragma unroll
            for (int mt = 0; mt < 4; mt++) {
                int r = wm * 64 + mt * 16 + grp;
                a2[0][mt][0] = asu[r * 36 + kb];
                a2[0][mt][1] = asu[(r + 8) * 36 + kb];
                a2[0][mt][2] = asu[r * 36 + kb + 4];
                a2[0][mt][3] = asu[(r + 8) * 36 + kb + 4];
            }
#pragma unroll
            for (int nt = 0; nt < 4; nt++) {
                int n = wn * 32 + nt * 8 + grp;
                b2[0][nt][0] = wsu[n * 36 + kb];
                b2[0][nt][1] = wsu[n * 36 + kb + 4];
            }
        }

#pragma unroll
        for (int kk = 0; kk < 4; kk++) {
            int cur = kk & 1, nxt = cur ^ 1;
            if (kk < 3) {
                int kb = tig + (kk + 1) * 8;
#pragma unroll
                for (int mt = 0; mt < 4; mt++) {
                    int r = wm * 64 + mt * 16 + grp;
                    a2[nxt][mt][0] = asu[r * 36 + kb];
                    a2[nxt][mt][1] = asu[(r + 8) * 36 + kb];
                    a2[nxt][mt][2] = asu[r * 36 + kb + 4];
                    a2[nxt][mt][3] = asu[(r + 8) * 36 + kb + 4];
                }
#pragma unroll
                for (int nt = 0; nt < 4; nt++) {
                    int n = wn * 32 + nt * 8 + grp;
                    b2[nxt][nt][0] = wsu[n * 36 + kb];
                    b2[nxt][nt][1] = wsu[n * 36 + kb + 4];
                }
            }
#pragma unroll
            for (int mt = 0; mt < 4; mt++)
#pragma unroll
                for (int nt = 0; nt < 4; nt++) {
                    asm volatile(
                        "mma.sync.aligned.m16n8k16.row.col.f32.f16.f16.f32 "
                        "{%0,%1,%2,%3}, {%4,%5,%6,%7}, {%8,%9}, {%0,%1,%2,%3};"
                        : "+f"(acc[mt][nt][0]), "+f"(acc[mt][nt][1]),
                          "+f"(acc[mt][nt][2]), "+f"(acc[mt][nt][3])
                        : "r"(a2[cur][mt][0]), "r"(a2[cur][mt][1]),
                          "r"(a2[cur][mt][2]), "r"(a2[cur][mt][3]),
                          "r"(b2[cur][nt][0]), "r"(b2[cur][nt][1]));
                }
        }
        __syncthreads();

        if (c + 2 < 8) {
            uint32_t ab = sbase + (uint32_t)(c & 1) * STGB;
            int k0 = (c + 2) * 64;
#pragma unroll
            for (int i = 0; i < 8; i++) cpa16(ab + sa[i],        A + aoff[i] + k0);
#pragma unroll
            for (int i = 0; i < 4; i++) cpa16(ab + ABYT + sw[i], W + woff[i] + k0);
            asm volatile("cp.async.commit_group;");
        }
    }

    if (emode == 0) {
        __half* C = (__half*)Cout;
#pragma unroll
        for (int mt = 0; mt < 4; mt++) {
            int r = m0 + wm * 64 + mt * 16 + grp;
#pragma unroll
            for (int nt = 0; nt < 4; nt++) {
                int cl = n0 + wn * 32 + nt * 8 + 2 * tig;
                float b0 = bias[cl], b1 = bias[cl + 1];
                __half2 p0 = __floats2half2_rn(acc[mt][nt][0] + b0, acc[mt][nt][1] + b1);
                __half2 p1 = __floats2half2_rn(acc[mt][nt][2] + b0, acc[mt][nt][3] + b1);
                *(__half2*)(C + (size_t)r * Nn + ncol0 + cl)       = p0;
                *(__half2*)(C + (size_t)(r + 8) * Nn + ncol0 + cl) = p1;
            }
        }
    } else {
#pragma unroll
        for (int mt = 0; mt < 4; mt++) {
            int r = m0 + wm * 64 + mt * 16 + grp;
#pragma unroll
            for (int nt = 0; nt < 4; nt++) {
                int cl = n0 + wn * 32 + nt * 8 + 2 * tig;
                int cc = cl >> 1;
                float b0 = bias[cl], b1 = bias[cl + 1];
                float nl1 = acc[mt][nt][0] + b0, gv1 = acc[mt][nt][1] + b1;
                float nl2 = acc[mt][nt][2] + b0, gv2 = acc[mt][nt][3] + b1;
                nl1 = nl1 > 0.f ? nl1 : 0.f;
                nl2 = nl2 > 0.f ? nl2 : 0.f;
                float sg1 = 1.f / (1.f + __expf(-gv1));
                float sg2 = 1.f / (1.f + __expf(-gv2));
                float old1 = __half2float(A[(size_t)r * 512 + cc]);
                float old2 = __half2float(A[(size_t)(r + 8) * 512 + cc]);
                float res1 = sg1 * old1 + (1.f - sg1) * nl1;
                float res2 = sg2 * old2 + (1.f - sg2) * nl2;
                if (emode == 1) {
                    __half* C = (__half*)Cout;
                    C[(size_t)r * 512 + cc]       = __float2half_rn(res1);
                    C[(size_t)(r + 8) * 512 + cc] = __float2half_rn(res2);
                } else {
                    float* C = (float*)Cout;
                    size_t o1 = (size_t)r * 1024 + coloff + cc;
                    size_t o2 = (size_t)(r + 8) * 1024 + coloff + cc;
                    C[o1] = res1; C[o2] = res2;
                    if (copies == 2) { C[total + o1] = res1; C[total + o2] = res2; }
                }
            }
        }
    }
}

// ---------------- banded attention: per-dir, 256-thr blocks, rows [16,528) ----------
__device__ __forceinline__ void ld8h(const __half* p, float* f) {
    uint4 u = *(const uint4*)p;
    float2 t;
    t = __half22float2(*(__half2*)&u.x); f[0] = t.x; f[1] = t.y;
    t = __half22float2(*(__half2*)&u.y); f[2] = t.x; f[3] = t.y;
    t = __half22float2(*(__half2*)&u.z); f[4] = t.x; f[5] = t.y;
    t = __half22float2(*(__half2*)&u.w); f[6] = t.x; f[7] = t.y;
}

__global__ __launch_bounds__(256) void attn_kernel(int dir) {
    int rem = blockIdx.x;
    int b = rem >> 6;
    int gblk = rem & 63;
    int sub = threadIdx.x >> 6;
    int h = threadIdx.x & 63;
    int i0 = WIDTHv + gblk * 8 + sub * 2;

    const __half* qkv = g_qkv + (size_t)(b * NPAD) * 3072 + dir * 1536 + h * 8;

    float q[2][8];
#pragma unroll
    for (int r = 0; r < 2; r++) ld8h(qkv + (size_t)(i0 + r) * 3072, q[r]);

    int jbase = dir ? i0 : i0 - WIDTHv - 1;

    float sum[2] = {0, 0};
    float o[2][8];
#pragma unroll
    for (int r = 0; r < 2; r++)
#pragma unroll
        for (int d = 0; d < 8; d++) o[r][d] = 0.f;

#pragma unroll
    for (int jidx = 0; jidx < 19; jidx++) {
        int j = jbase + jidx;
        bool jr = (j >= 0) && (j < NPAD);
        float k[8], v[8];
        if (jr) {
            ld8h(qkv + (size_t)j * 3072 + 512,  k);
            ld8h(qkv + (size_t)j * 3072 + 1024, v);
        }
#pragma unroll
        for (int r = 0; r < 2; r++) {
            int jj = jidx - r;
            if (jj >= 0 && jj < 18 && jr) {
                float s = q[r][0]*k[0] + q[r][1]*k[1] + q[r][2]*k[2] + q[r][3]*k[3]
                        + q[r][4]*k[4] + q[r][5]*k[5] + q[r][6]*k[6] + q[r][7]*k[7];
                float p = __expf(s * 0.35355339059327373f);
                sum[r] += p;
#pragma unroll
                for (int d = 0; d < 8; d++) o[r][d] += p * v[d];
            }
        }
    }
#pragma unroll
    for (int r = 0; r < 2; r++) {
        float inv = 1.f / sum[r];
        uint4 u;
        __half2 h0 = __floats2half2_rn(o[r][0] * inv, o[r][1] * inv);
        __half2 h1 = __floats2half2_rn(o[r][2] * inv, o[r][3] * inv);
        __half2 h2 = __floats2half2_rn(o[r][4] * inv, o[r][5] * inv);
        __half2 h3 = __floats2half2_rn(o[r][6] * inv, o[r][7] * inv);
        u.x = *(uint32_t*)&h0; u.y = *(uint32_t*)&h1;
        u.z = *(uint32_t*)&h2; u.w = *(uint32_t*)&h3;
        *(uint4*)(g_attn + ((size_t)dir * MQKV + b * NPAD + i0 + r) * 512 + h * 8) = u;
    }
}

// ---------------- launcher: round-14 structure (single prep, two streams) ----------
extern "C" void kernel_launch(void* const* d_in, const int* in_sizes, int n_in,
                              void* d_out, int out_size) {
    __half *xp, *qkvp, *attnp, *h0a, *h0b, *wcp;
    float *bp;
    cudaGetSymbolAddress((void**)&xp,   g_x);
    cudaGetSymbolAddress((void**)&qkvp, g_qkv);
    cudaGetSymbolAddress((void**)&attnp,g_attn);
    cudaGetSymbolAddress((void**)&h0a,  g_h0a);
    cudaGetSymbolAddress((void**)&h0b,  g_h0b);
    cudaGetSymbolAddress((void**)&wcp,  g_wcvt);
    cudaGetSymbolAddress((void**)&bp,   g_bias);

    static cudaStream_t s1 = nullptr;
    static cudaEvent_t evF = nullptr, evJ = nullptr;
    if (!s1) {
        cudaStreamCreateWithFlags(&s1, cudaStreamNonBlocking);
        cudaEventCreateWithFlags(&evF, cudaEventDisableTiming);
        cudaEventCreateWithFlags(&evJ, cudaEventDisableTiming);
        cudaFuncSetAttribute(gemm_mma, cudaFuncAttributeMaxDynamicSharedMemorySize, 55296);
    }

    long total = (long)MS * 1024;
    int copies = ((long)out_size >= 2 * total) ? 2 : 1;

    prep_kernel<<<(PREP_P4 + 255) / 256, 256>>>(
        (const float*)d_in[0], (const float*)d_in[1], (const float*)d_in[2],
        (const float*)d_in[3], (const float*)d_in[7],
        (const float*)d_in[5], (const float*)d_in[9],
        (const float*)d_in[11], (const float*)d_in[13],
        (const float*)d_in[4], (const float*)d_in[8],
        (const float*)d_in[6], (const float*)d_in[10],
        (const float*)d_in[12], (const float*)d_in[14]);

    cudaEventRecord(evF, 0);
    cudaStreamWaitEvent(s1, evF, 0);

    for (int dir = 0; dir < 2; dir++) {
        cudaStream_t st = dir ? s1 : 0;
        size_t adoff = (size_t)dir * MQKV * 512;
        size_t hdoff = (size_t)dir * MS * 512;

        gemm_mma<<<dim3(24, 34), 128, 55296, st>>>(
            xp, wcp + (size_t)dir * 786432, bp + dir * 1536, qkvp, 3072,
            0, dir * 1536, 0, 0, 0, 0);

        attn_kernel<<<512, 256, 0, st>>>(dir);

        gemm_mma<<<dim3(8, 32), 128, 55296, st>>>(
            attnp + adoff, wcp + WOFF_WO + (size_t)dir * 262144,
            bp + BOFF_WO + dir * 512, h0a + hdoff, 512,
            1, 0, 0, 0, 0, 0);

        gemm_mma<<<dim3(16, 32), 128, 55296, st>>>(
            h0a + hdoff, wcp + WOFF_HW + (size_t)(dir * 2) * 524288,
            bp + BOFF_HW + dir * 2048, h0b + hdoff, 1024,
            0, 0, 1, 0, 0, 0);

        gemm_mma<<<dim3(16, 32), 128, 55296, st>>>(
            h0b + hdoff, wcp + WOFF_HW + (size_t)(dir * 2 + 1) * 524288,
            bp + BOFF_HW + dir * 2048 + 1024, d_out, 1024,
            0, 0, 2, total, copies, dir * 512);
    }

    cudaEventRecord(evJ, s1);
    cudaStreamWaitEvent(0, evJ, 0);
}

// round 17
// speedup vs baseline: 1.0250x; 1.0250x over previous
#include <cuda_runtime.h>
#include <cuda_fp16.h>
#include <cstdint>
#include <math.h>

#define Bv      8
#define Sv      512
#define Dv      512
#define WIDTHv  16
#define NPAD    544
#define MQKV    (Bv*NPAD)      // 4352
#define MS      (Bv*Sv)        // 4096
#define M2      (2*MS)         // 8192

#define WOFF_QKV 0
#define WOFF_WO  1572864
#define WOFF_HW  2097152
#define BOFF_QKV 0
#define BOFF_WO  3072
#define BOFF_HW  4096

// ---------------- scratch (half activations/weights) ---------------------------
__device__ __half g_x[MQKV*Dv];
__device__ __half g_qkv[MQKV*3072];
__device__ __half g_attn[2*MQKV*Dv];
__device__ __half g_h0a[M2*Dv];
__device__ __half g_h0b[M2*Dv];
__device__ __half g_wcvt[4194304];
__device__ float  g_bias[8192];

// ---------------- helpers -------------------------------------------------------
__device__ __forceinline__ uint32_t smem_u32(const void* p) {
    uint32_t a;
    asm("{ .reg .u64 t; cvta.to.shared.u64 t, %1; cvt.u32.u64 %0, t; }"
        : "=r"(a) : "l"(p));
    return a;
}
__device__ __forceinline__ void cpa16(uint32_t s, const void* g) {
    asm volatile("cp.async.cg.shared.global [%0], [%1], 16;" :: "r"(s), "l"(g));
}

// ---------------- prep (4 floats/thread, all weights+biases+pad) -------------------
#define PREP_W4   1048576
#define PREP_B    (PREP_W4 + 8192)
#define PREP_P4   (PREP_B + MQKV*Dv/4)

__global__ void prep_kernel(
    const float* __restrict__ inp,
    const float* __restrict__ lp,  const float* __restrict__ rp,
    const float* __restrict__ Wq0, const float* __restrict__ Wq1,
    const float* __restrict__ Wo0, const float* __restrict__ Wo1,
    const float* __restrict__ Wh0, const float* __restrict__ Wh1,
    const float* __restrict__ bq0, const float* __restrict__ bq1,
    const float* __restrict__ bo0, const float* __restrict__ bo1,
    const float* __restrict__ bh0, const float* __restrict__ bh1)
{
    int t = blockIdx.x * 256 + threadIdx.x;
    if (t < PREP_W4) {
        int i = t * 4;
        const float* src;
        if (i < WOFF_WO) {
            int n = i >> 9, k = i & 511;
            int d = n >= 1536;
            src = (d ? Wq1 : Wq0) + (n - d * 1536) * 512 + k;
        } else if (i < WOFF_HW) {
            int j = i - WOFF_WO;
            int n = j >> 9, k = j & 511;
            int d = n >= 512;
            src = (d ? Wo1 : Wo0) + (n - d * 512) * 512 + k;
        } else {
            int j = i - WOFF_HW;
            int blk = j >> 19;
            int d = blk >> 1, l = blk & 1;
            int rw = (j >> 9) & 1023, k = j & 511;
            int c = rw >> 1, wh = rw & 1;
            src = (d ? Wh1 : Wh0) + l * 524288 + (wh * 512 + c) * 512 + k;
        }
        float4 v = *(const float4*)src;
        __half2 a = __floats2half2_rn(v.x, v.y);
        __half2 b = __floats2half2_rn(v.z, v.w);
        uint2 u = {*(uint32_t*)&a, *(uint32_t*)&b};
        *(uint2*)(g_wcvt + i) = u;
    } else if (t < PREP_B) {
        int j = t - PREP_W4;
        float v;
        if (j < BOFF_WO) {
            int d = j >= 1536;
            v = (d ? bq1 : bq0)[j - d * 1536];
        } else if (j < BOFF_HW) {
            int jj = j - BOFF_WO;
            int d = jj >= 512;
            v = (d ? bo1 : bo0)[jj - d * 512];
        } else {
            int jj = j - BOFF_HW;
            int blk = jj >> 10;
            int d = blk >> 1, l = blk & 1;
            int r = jj & 1023;
            int c = r >> 1, wh = r & 1;
            v = (d ? bh1 : bh0)[l * 1024 + wh * 512 + c];
        }
        g_bias[j] = v;
    } else if (t < PREP_P4) {
        int idx = (t - PREP_B) * 4;
        int d = idx & (Dv - 1);
        int p = (idx / Dv) % NPAD;
        int b = idx / (Dv * NPAD);
        const float* src;
        if (p < WIDTHv)            src = lp + p * Dv + d;
        else if (p < WIDTHv + Sv)  src = inp + ((size_t)b * Sv + (p - WIDTHv)) * Dv + d;
        else                       src = rp + (p - WIDTHv - Sv) * Dv + d;
        float4 v = *(const float4*)src;
        __half2 a = __floats2half2_rn(v.x, v.y);
        __half2 bb = __floats2half2_rn(v.z, v.w);
        uint2 u = {*(uint32_t*)&a, *(uint32_t*)&bb};
        *(uint2*)(g_x + idx) = u;
    }
}

// ---------------- fp16 mma GEMM: BM=128 BN=64 BK=64, 128 thr, 2-stage --------------
// (round-14 configuration — measured best under stream overlap; do not reshape)
#define ABYT   18432
#define STGB   27648

__global__ __launch_bounds__(128, 4) void gemm_mma(
    const __half* __restrict__ A, const __half* __restrict__ W,
    const float* __restrict__ bias, void* __restrict__ Cout,
    int Nn, int amap, int ncol0,
    int emode, long total, int copies, int coloff)
{
    extern __shared__ char dsm[];
    uint32_t sbase = smem_u32(dsm);
    int tid = threadIdx.x;
    int m0 = blockIdx.y * 128, n0 = blockIdx.x * 64;

    long aoff[8]; int woff[4];
    uint32_t sa[8], sw[4];
#pragma unroll
    for (int i = 0; i < 8; i++) {
        int id = tid + 128 * i;
        int row = id >> 3, seg = id & 7;
        int gm = m0 + row;
        long ar = amap ? ((long)(gm >> 9) * NPAD + WIDTHv + (gm & 511)) : (long)gm;
        aoff[i] = ar * 512 + seg * 8;
        sa[i] = (uint32_t)(row * 144 + seg * 16);
    }
#pragma unroll
    for (int i = 0; i < 4; i++) {
        int id = tid + 128 * i;
        int row = id >> 3, seg = id & 7;
        woff[i] = (n0 + row) * 512 + seg * 8;
        sw[i] = (uint32_t)(row * 144 + seg * 16);
    }

#pragma unroll
    for (int s = 0; s < 2; s++) {
        uint32_t ab = sbase + (uint32_t)s * STGB;
#pragma unroll
        for (int i = 0; i < 8; i++) cpa16(ab + sa[i],        A + aoff[i] + s * 64);
#pragma unroll
        for (int i = 0; i < 4; i++) cpa16(ab + ABYT + sw[i], W + woff[i] + s * 64);
        asm volatile("cp.async.commit_group;");
    }

    int wid = tid >> 5, lane = tid & 31;
    int wm = wid >> 1, wn = wid & 1;
    int grp = lane >> 2, tig = lane & 3;

    float acc[4][4][4];
#pragma unroll
    for (int mt = 0; mt < 4; mt++)
#pragma unroll
        for (int nt = 0; nt < 4; nt++)
#pragma unroll
            for (int r = 0; r < 4; r++) acc[mt][nt][r] = 0.f;

    for (int c = 0; c < 8; c++) {
        if (c >= 7) asm volatile("cp.async.wait_group 0;" ::: "memory");
        else        asm volatile("cp.async.wait_group 1;" ::: "memory");
        __syncthreads();

        const uint32_t* asu = (const uint32_t*)(dsm + (size_t)(c & 1) * STGB);
        const uint32_t* wsu = asu + ABYT / 4;

#pragma unroll
        for (int kk = 0; kk < 4; kk++) {
            int kb = tig + kk * 8;
            uint32_t a[4][4], b[4][2];
#pragma unroll
            for (int mt = 0; mt < 4; mt++) {
                int r = wm * 64 + mt * 16 + grp;
                a[mt][0] = asu[r * 36 + kb];
                a[mt][1] = asu[(r + 8) * 36 + kb];
                a[mt][2] = asu[r * 36 + kb + 4];
                a[mt][3] = asu[(r + 8) * 36 + kb + 4];
            }
#pragma unroll
            for (int nt = 0; nt < 4; nt++) {
                int n = wn * 32 + nt * 8 + grp;
                b[nt][0] = wsu[n * 36 + kb];
                b[nt][1] = wsu[n * 36 + kb + 4];
            }
#pragma unroll
            for (int mt = 0; mt < 4; mt++)
#pragma unroll
                for (int nt = 0; nt < 4; nt++) {
                    asm volatile(
                        "mma.sync.aligned.m16n8k16.row.col.f32.f16.f16.f32 "
                        "{%0,%1,%2,%3}, {%4,%5,%6,%7}, {%8,%9}, {%0,%1,%2,%3};"
                        : "+f"(acc[mt][nt][0]), "+f"(acc[mt][nt][1]),
                          "+f"(acc[mt][nt][2]), "+f"(acc[mt][nt][3])
                        : "r"(a[mt][0]), "r"(a[mt][1]), "r"(a[mt][2]), "r"(a[mt][3]),
                          "r"(b[nt][0]), "r"(b[nt][1]));
                }
        }
        __syncthreads();

        if (c + 2 < 8) {
            uint32_t ab = sbase + (uint32_t)(c & 1) * STGB;
            int k0 = (c + 2) * 64;
#pragma unroll
            for (int i = 0; i < 8; i++) cpa16(ab + sa[i],        A + aoff[i] + k0);
#pragma unroll
            for (int i = 0; i < 4; i++) cpa16(ab + ABYT + sw[i], W + woff[i] + k0);
            asm volatile("cp.async.commit_group;");
        }
    }

    if (emode == 0) {
        __half* C = (__half*)Cout;
#pragma unroll
        for (int mt = 0; mt < 4; mt++) {
            int r = m0 + wm * 64 + mt * 16 + grp;
#pragma unroll
            for (int nt = 0; nt < 4; nt++) {
                int cl = n0 + wn * 32 + nt * 8 + 2 * tig;
                float b0 = bias[cl], b1 = bias[cl + 1];
                __half2 p0 = __floats2half2_rn(acc[mt][nt][0] + b0, acc[mt][nt][1] + b1);
                __half2 p1 = __floats2half2_rn(acc[mt][nt][2] + b0, acc[mt][nt][3] + b1);
                *(__half2*)(C + (size_t)r * Nn + ncol0 + cl)       = p0;
                *(__half2*)(C + (size_t)(r + 8) * Nn + ncol0 + cl) = p1;
            }
        }
    } else {
#pragma unroll
        for (int mt = 0; mt < 4; mt++) {
            int r = m0 + wm * 64 + mt * 16 + grp;
#pragma unroll
            for (int nt = 0; nt < 4; nt++) {
                int cl = n0 + wn * 32 + nt * 8 + 2 * tig;
                int cc = cl >> 1;
                float b0 = bias[cl], b1 = bias[cl + 1];
                float nl1 = acc[mt][nt][0] + b0, gv1 = acc[mt][nt][1] + b1;
                float nl2 = acc[mt][nt][2] + b0, gv2 = acc[mt][nt][3] + b1;
                nl1 = nl1 > 0.f ? nl1 : 0.f;
                nl2 = nl2 > 0.f ? nl2 : 0.f;
                float sg1 = 1.f / (1.f + __expf(-gv1));
                float sg2 = 1.f / (1.f + __expf(-gv2));
                float old1 = __half2float(A[(size_t)r * 512 + cc]);
                float old2 = __half2float(A[(size_t)(r + 8) * 512 + cc]);
                float res1 = sg1 * old1 + (1.f - sg1) * nl1;
                float res2 = sg2 * old2 + (1.f - sg2) * nl2;
                if (emode == 1) {
                    __half* C = (__half*)Cout;
                    C[(size_t)r * 512 + cc]       = __float2half_rn(res1);
                    C[(size_t)(r + 8) * 512 + cc] = __float2half_rn(res2);
                } else {
                    float* C = (float*)Cout;
                    size_t o1 = (size_t)r * 1024 + coloff + cc;
                    size_t o2 = (size_t)(r + 8) * 1024 + coloff + cc;
                    C[o1] = res1; C[o2] = res2;
                    if (copies == 2) { C[total + o1] = res1; C[total + o2] = res2; }
                }
            }
        }
    }
}

// ---------------- banded attention: per-dir, 256-thr blocks, rows [16,528) ----------
__device__ __forceinline__ void ld8h(const __half* p, float* f) {
    uint4 u = *(const uint4*)p;
    float2 t;
    t = __half22float2(*(__half2*)&u.x); f[0] = t.x; f[1] = t.y;
    t = __half22float2(*(__half2*)&u.y); f[2] = t.x; f[3] = t.y;
    t = __half22float2(*(__half2*)&u.z); f[4] = t.x; f[5] = t.y;
    t = __half22float2(*(__half2*)&u.w); f[6] = t.x; f[7] = t.y;
}

__global__ __launch_bounds__(256) void attn_kernel(int dir) {
    int rem = blockIdx.x;
    int b = rem >> 6;
    int gblk = rem & 63;
    int sub = threadIdx.x >> 6;
    int h = threadIdx.x & 63;
    int i0 = WIDTHv + gblk * 8 + sub * 2;

    const __half* qkv = g_qkv + (size_t)(b * NPAD) * 3072 + dir * 1536 + h * 8;

    float q[2][8];
#pragma unroll
    for (int r = 0; r < 2; r++) ld8h(qkv + (size_t)(i0 + r) * 3072, q[r]);

    int jbase = dir ? i0 : i0 - WIDTHv - 1;
    // incremental K/V pointer: one IADD per iteration instead of IMAD chain
    const __half* kvp = qkv + (size_t)jbase * 3072 + 512;

    float sum[2] = {0, 0};
    float o[2][8];
#pragma unroll
    for (int r = 0; r < 2; r++)
#pragma unroll
        for (int d = 0; d < 8; d++) o[r][d] = 0.f;

#pragma unroll
    for (int jidx = 0; jidx < 19; jidx++) {
        int j = jbase + jidx;
        bool jr = (j >= 0) && (j < NPAD);
        float k[8], v[8];
        if (jr) {
            ld8h(kvp,       k);
            ld8h(kvp + 512, v);
        }
#pragma unroll
        for (int r = 0; r < 2; r++) {
            int jj = jidx - r;
            if (jj >= 0 && jj < 18 && jr) {
                float s = q[r][0]*k[0] + q[r][1]*k[1] + q[r][2]*k[2] + q[r][3]*k[3]
                        + q[r][4]*k[4] + q[r][5]*k[5] + q[r][6]*k[6] + q[r][7]*k[7];
                float p = __expf(s * 0.35355339059327373f);
                sum[r] += p;
#pragma unroll
                for (int d = 0; d < 8; d++) o[r][d] += p * v[d];
            }
        }
        kvp += 3072;
    }
    __half* ob = g_attn + ((size_t)dir * MQKV + b * NPAD + i0) * 512 + h * 8;
#pragma unroll
    for (int r = 0; r < 2; r++) {
        float inv = 1.f / sum[r];
        uint4 u;
        __half2 h0 = __floats2half2_rn(o[r][0] * inv, o[r][1] * inv);
        __half2 h1 = __floats2half2_rn(o[r][2] * inv, o[r][3] * inv);
        __half2 h2 = __floats2half2_rn(o[r][4] * inv, o[r][5] * inv);
        __half2 h3 = __floats2half2_rn(o[r][6] * inv, o[r][7] * inv);
        u.x = *(uint32_t*)&h0; u.y = *(uint32_t*)&h1;
        u.z = *(uint32_t*)&h2; u.w = *(uint32_t*)&h3;
        *(uint4*)(ob + (size_t)r * 512) = u;
    }
}

// ---------------- launcher: single prep, two per-dir stream pipelines --------------
extern "C" void kernel_launch(void* const* d_in, const int* in_sizes, int n_in,
                              void* d_out, int out_size) {
    __half *xp, *qkvp, *attnp, *h0a, *h0b, *wcp;
    float *bp;
    cudaGetSymbolAddress((void**)&xp,   g_x);
    cudaGetSymbolAddress((void**)&qkvp, g_qkv);
    cudaGetSymbolAddress((void**)&attnp,g_attn);
    cudaGetSymbolAddress((void**)&h0a,  g_h0a);
    cudaGetSymbolAddress((void**)&h0b,  g_h0b);
    cudaGetSymbolAddress((void**)&wcp,  g_wcvt);
    cudaGetSymbolAddress((void**)&bp,   g_bias);

    static cudaStream_t s1 = nullptr;
    static cudaEvent_t evF = nullptr, evJ = nullptr;
    if (!s1) {
        cudaStreamCreateWithFlags(&s1, cudaStreamNonBlocking);
        cudaEventCreateWithFlags(&evF, cudaEventDisableTiming);
        cudaEventCreateWithFlags(&evJ, cudaEventDisableTiming);
        cudaFuncSetAttribute(gemm_mma, cudaFuncAttributeMaxDynamicSharedMemorySize, 55296);
    }

    long total = (long)MS * 1024;
    int copies = ((long)out_size >= 2 * total) ? 2 : 1;

    prep_kernel<<<(PREP_P4 + 255) / 256, 256>>>(
        (const float*)d_in[0], (const float*)d_in[1], (const float*)d_in[2],
        (const float*)d_in[3], (const float*)d_in[7],
        (const float*)d_in[5], (const float*)d_in[9],
        (const float*)d_in[11], (const float*)d_in[13],
        (const float*)d_in[4], (const float*)d_in[8],
        (const float*)d_in[6], (const float*)d_in[10],
        (const float*)d_in[12], (const float*)d_in[14]);

    cudaEventRecord(evF, 0);
    cudaStreamWaitEvent(s1, evF, 0);

    for (int dir = 0; dir < 2; dir++) {
        cudaStream_t st = dir ? s1 : 0;
        size_t adoff = (size_t)dir * MQKV * 512;
        size_t hdoff = (size_t)dir * MS * 512;

        gemm_mma<<<dim3(24, 34), 128, 55296, st>>>(
            xp, wcp + (size_t)dir * 786432, bp + dir * 1536, qkvp, 3072,
            0, dir * 1536, 0, 0, 0, 0);

        attn_kernel<<<512, 256, 0, st>>>(dir);

        gemm_mma<<<dim3(8, 32), 128, 55296, st>>>(
            attnp + adoff, wcp + WOFF_WO + (size_t)dir * 262144,
            bp + BOFF_WO + dir * 512, h0a + hdoff, 512,
            1, 0, 0, 0, 0, 0);

        gemm_mma<<<dim3(16, 32), 128, 55296, st>>>(
            h0a + hdoff, wcp + WOFF_HW + (size_t)(dir * 2) * 524288,
            bp + BOFF_HW + dir * 2048, h0b + hdoff, 1024,
            0, 0, 1, 0, 0, 0);

        gemm_mma<<<dim3(16, 32), 128, 55296, st>>>(
            h0b + hdoff, wcp + WOFF_HW + (size_t)(dir * 2 + 1) * 524288,
            bp + BOFF_HW + dir * 2048 + 1024, d_out, 1024,
            0, 0, 2, total, copies, dir * 512);
    }

    cudaEventRecord(evJ, s1);
    cudaStreamWaitEvent(0, evJ, 0);
}